// round 13
// baseline (speedup 1.0000x reference)
#include <cuda_runtime.h>
#include <cuda_fp16.h>
#include <cstdint>
#include <cstddef>

// ---------------- problem constants ----------------
#define TOKENS 8192
#define IN_F   4096
#define OUT_F  11008

// ---------------- GEMM tiling ----------------
#define BM 128
#define BN 128
#define BK 64
#define STAGES 3
#define KITERS (IN_F / BK)          // 64
#define NTHREADS 160                // warps 0-3: MMA (2x2, 64x64); warp 4: producer

// SMEM layout (byte offsets from 1024-aligned base)
#define OFF_A      0                         // 3 x 16384 (A fp16, SW128)
#define OFF_B      (OFF_A + STAGES * 16384)  // 3 x 16384 (B fp16, SW128)
#define SMEM_USED  (OFF_B + STAGES * 16384)  // 98304
#define SMEM_BYTES (SMEM_USED + 1024)        // 99328 -> 2 CTAs/SM

// ---------------- scratch (static device global; no allocation) ----------------
// x fp16, octet-permuted: pos p of each 8-k octet holds x[oct*8 + perm[p]],
// perm = [0,4,1,5,2,6,3,7]; B dequant emits the same permutation -> GEMM invariant.
__device__ __align__(1024) __half g_X[(size_t)TOKENS * IN_F]; // 67 MB

// ---------------- PTX helpers (baseline sm_80+ only) ----------------
__device__ __forceinline__ uint32_t smem_u32(const void* p) {
    uint32_t a;
    asm("{ .reg .u64 t; cvta.to.shared.u64 t, %1; cvt.u32.u64 %0, t; }" : "=r"(a) : "l"(p));
    return a;
}
__device__ __forceinline__ void cp_async16(uint32_t dst, const void* src) {
    asm volatile("cp.async.cg.shared.global [%0], [%1], 16;" :: "r"(dst), "l"(src) : "memory");
}
__device__ __forceinline__ void cp_commit() {
    asm volatile("cp.async.commit_group;" ::: "memory");
}
template <int N> __device__ __forceinline__ void cp_wait() {
    asm volatile("cp.async.wait_group %0;" :: "n"(N) : "memory");
}
__device__ __forceinline__ void bar_sync(int id) {
    asm volatile("bar.sync %0, %1;" :: "r"(id), "n"(NTHREADS) : "memory");
}
__device__ __forceinline__ void bar_arrive(int id) {
    asm volatile("bar.arrive %0, %1;" :: "r"(id), "n"(NTHREADS) : "memory");
}
__device__ __forceinline__ void ldsm_x4(uint32_t& r0, uint32_t& r1, uint32_t& r2, uint32_t& r3,
                                        uint32_t addr) {
    asm volatile("ldmatrix.sync.aligned.m8n8.x4.shared.b16 {%0,%1,%2,%3}, [%4];"
                 : "=r"(r0), "=r"(r1), "=r"(r2), "=r"(r3) : "r"(addr));
}
__device__ __forceinline__ void sts128(uint32_t addr, uint32_t r0, uint32_t r1,
                                       uint32_t r2, uint32_t r3) {
    asm volatile("st.shared.v4.b32 [%0], {%1,%2,%3,%4};"
                 :: "r"(addr), "r"(r0), "r"(r1), "r"(r2), "r"(r3) : "memory");
}
__device__ __forceinline__ void mma16816(float* c, const uint32_t* a, const uint32_t* b) {
    asm volatile(
        "mma.sync.aligned.m16n8k16.row.col.f32.f16.f16.f32 "
        "{%0,%1,%2,%3}, {%4,%5,%6,%7}, {%8,%9}, {%0,%1,%2,%3};"
        : "+f"(c[0]), "+f"(c[1]), "+f"(c[2]), "+f"(c[3])
        : "r"(a[0]), "r"(a[1]), "r"(a[2]), "r"(a[3]), "r"(b[0]), "r"(b[1]));
}

// SW128 swizzle on byte offset within a tile (128B rows)
#define SWZ(o) ((o) ^ (((o) >> 3) & 0x70))

// ---------------- kernel 1: x fp32 -> fp16, octet-permuted ----------------
__global__ void __launch_bounds__(256) xconv_kernel(const float* __restrict__ x) {
    size_t i = (size_t)blockIdx.x * blockDim.x + threadIdx.x;  // one octet each
    const float4* p = (const float4*)(x + i * 8);
    float4 v0 = p[0];
    float4 v1 = p[1];
    union { __half2 h[4]; uint4 u; } r;
    r.h[0] = __floats2half2_rn(v0.x, v1.x);
    r.h[1] = __floats2half2_rn(v0.y, v1.y);
    r.h[2] = __floats2half2_rn(v0.z, v1.z);
    r.h[3] = __floats2half2_rn(v0.w, v1.w);
    ((uint4*)g_X)[i] = r.u;
}

// ---------------- kernel 2: warp-specialized fused dequant + HMMA GEMM ----------
__global__ void __launch_bounds__(NTHREADS, 2) gemm_kernel(const int* __restrict__ qw,
                                                           const int* __restrict__ qz,
                                                           const float* __restrict__ sc,
                                                           const float* __restrict__ bias,
                                                           float* __restrict__ out) {
    extern __shared__ char dynsmem_raw[];
    const int tid = threadIdx.x;
    const int wid = tid >> 5;
    const int lid = tid & 31;
    const int m0 = blockIdx.x * BM;   // 64 m-tiles
    const int n0 = blockIdx.y * BN;   // 86 n-tiles

    uint32_t sb0 = smem_u32(dynsmem_raw);
    uint32_t sb  = (sb0 + 1023) & ~1023u;            // 1024-aligned base

    if (wid == 4) {
        // ================= PRODUCER WARP =================
        const __half* gA = g_X + (size_t)m0 * IN_F;
        uint32_t rawreg[2][32];     // [buf][kp*4+c']  raw qweight words
        float    scv[2][4];         // [buf][c']       scales
        uint32_t zwv[2][4];         // [buf][c']       qzero words
        const int sh = (lid & 7) * 4;

        // load raw/scale/zero for stage j into buffer buf (LDG -> regs)
        auto ldg_stage = [&](int j, int buf) {
            const int g = (j * BK) >> 7;
#pragma unroll
            for (int c = 0; c < 4; ++c) {
                int nn = n0 + lid + 32 * c;
                scv[buf][c] = __ldg(sc + (size_t)g * OUT_F + nn);
                zwv[buf][c] = (uint32_t)__ldg(qz + (size_t)g * (OUT_F / 8) + (nn >> 3));
#pragma unroll
                for (int kp = 0; kp < 8; ++kp)
                    rawreg[buf][kp * 4 + c] =
                        (uint32_t)__ldg(qw + (size_t)(j * 8 + kp) * OUT_F + nn);
            }
        };
        // dequant buffer buf into B slot s (conflict-free STS: n = lid + 32c)
        auto dequant = [&](int buf, int s) {
            uint32_t bBase = sb + OFF_B + s * 16384;
#pragma unroll
            for (int c = 0; c < 4; ++c) {
                int n = lid + 32 * c;
                int z = (int)((zwv[buf][c] >> sh) & 15u);
                __half2 s2  = __float2half2_rn(scv[buf][c]);
                __half2 hz2 = __float2half2_rn(1024.0f + (float)z);
#pragma unroll
                for (int kp = 0; kp < 8; ++kp) {
                    uint32_t w = rawreg[buf][kp * 4 + c];
                    uint32_t q0 = (w & 0x000F000Fu) | 0x64006400u;
                    uint32_t q1 = ((w >> 4)  & 0x000F000Fu) | 0x64006400u;
                    uint32_t q2 = ((w >> 8)  & 0x000F000Fu) | 0x64006400u;
                    uint32_t q3 = ((w >> 12) & 0x000F000Fu) | 0x64006400u;
                    union { __half2 h; uint32_t u; } r0, r1, r2, r3;
                    r0.h = __hmul2(__hsub2(*(__half2*)&q0, hz2), s2);
                    r1.h = __hmul2(__hsub2(*(__half2*)&q1, hz2), s2);
                    r2.h = __hmul2(__hsub2(*(__half2*)&q2, hz2), s2);
                    r3.h = __hmul2(__hsub2(*(__half2*)&q3, hz2), s2);
                    sts128(bBase + SWZ((uint32_t)(n * 128 + kp * 16)),
                           r0.u, r1.u, r2.u, r3.u);
                }
            }
        };

        ldg_stage(0, 0);  // raw(0) -> buf 0
        for (int j = 0; j < KITERS; ++j) {
            const int s   = j % STAGES;
            const int buf = j & 1;
            if (j >= STAGES) bar_sync(4 + s);   // consumers freed slot (stage j-3 done)
            // A(j) -> slot s via cp.async (1024 chunks / 32 threads)
            {
                uint32_t aBase = sb + OFF_A + s * 16384;
                const __half* gAk = gA + j * BK;
#pragma unroll
                for (int it = 0; it < 32; ++it) {
                    int chunk = lid + it * 32;
                    int r = chunk >> 3, c = chunk & 7;
                    cp_async16(aBase + SWZ((uint32_t)(r * 128 + c * 16)),
                               gAk + (size_t)r * IN_F + c * 8);
                }
                cp_commit();
            }
            if (j + 1 < KITERS) ldg_stage(j + 1, buf ^ 1);  // prefetch next raw
            dequant(buf, s);                                 // B(j) -> slot s
            cp_wait<0>();                                    // A(j) landed
            bar_arrive(1 + s);                               // publish FULL(j)
        }
    } else {
        // ================= CONSUMER WARPS (0-3) =================
        const int wm = wid & 1;       // 2 m-warps (64 rows each)
        const int wn = wid >> 1;      // 2 n-warps (64 cols each)

        float acc[4][8][4];
#pragma unroll
        for (int mi = 0; mi < 4; ++mi)
#pragma unroll
            for (int ni = 0; ni < 8; ++ni)
#pragma unroll
                for (int q = 0; q < 4; ++q) acc[mi][ni][q] = 0.0f;

        const int aRow = wm * 64 + (lid & 15);            // + mi*16
        const int aChk = lid >> 4;                        // + 2*kk
        const int bRow = wn * 64 + (lid & 7) + ((lid >> 4) & 1) * 8;  // + nj*16
        const int bChk = (lid >> 3) & 1;                  // + 2*kk

        for (int j = 0; j < KITERS; ++j) {
            const int s = j % STAGES;
            bar_sync(1 + s);                              // FULL(j): A+B ready
            const uint32_t aT = sb + OFF_A + s * 16384;
            const uint32_t bT = sb + OFF_B + s * 16384;
#pragma unroll
            for (int kk = 0; kk < BK / 16; ++kk) {
                uint32_t a[4][4];
#pragma unroll
                for (int mi = 0; mi < 4; ++mi) {
                    uint32_t ad = aT + SWZ((uint32_t)((aRow + mi * 16) * 128 + (2 * kk + aChk) * 16));
                    ldsm_x4(a[mi][0], a[mi][1], a[mi][2], a[mi][3], ad);
                }
                uint32_t b[8][2];
#pragma unroll
                for (int nj = 0; nj < 4; ++nj) {
                    uint32_t bd = bT + SWZ((uint32_t)((bRow + nj * 16) * 128 + (2 * kk + bChk) * 16));
                    uint32_t r0, r1, r2, r3;
                    ldsm_x4(r0, r1, r2, r3, bd);
                    b[2 * nj][0] = r0;     b[2 * nj][1] = r1;
                    b[2 * nj + 1][0] = r2; b[2 * nj + 1][1] = r3;
                }
#pragma unroll
                for (int mi = 0; mi < 4; ++mi)
#pragma unroll
                    for (int ni = 0; ni < 8; ++ni)
                        mma16816(acc[mi][ni], a[mi], b[ni]);
            }
            if (j + STAGES < KITERS) bar_arrive(4 + s);   // EMPTY(slot s)
        }

        // ---- epilogue: direct stores with bias ----
        const int mw = m0 + wm * 64;
        const int nw = n0 + wn * 64;
        const int rsub = lid >> 2;
        const int csub = (lid & 3) * 2;
#pragma unroll
        for (int mi = 0; mi < 4; ++mi) {
#pragma unroll
            for (int ni = 0; ni < 8; ++ni) {
                int col = nw + ni * 8 + csub;
                float2 bv = *(const float2*)(bias + col);
                int r0 = mw + mi * 16 + rsub;
                float2 v0 = { acc[mi][ni][0] + bv.x, acc[mi][ni][1] + bv.y };
                *(float2*)(out + (size_t)r0 * OUT_F + col) = v0;
                float2 v1 = { acc[mi][ni][2] + bv.x, acc[mi][ni][3] + bv.y };
                *(float2*)(out + (size_t)(r0 + 8) * OUT_F + col) = v1;
            }
        }
    }
}

// ---------------- launch ----------------
extern "C" void kernel_launch(void* const* d_in, const int* in_sizes, int n_in,
                              void* d_out, int out_size) {
    const float* x    = (const float*)d_in[0];
    const int*   qw   = (const int*)d_in[1];
    const int*   qz   = (const int*)d_in[2];
    const float* sc   = (const float*)d_in[3];
    const float* bias = (const float*)d_in[4];
    float* out = (float*)d_out;

    cudaFuncSetAttribute(gemm_kernel, cudaFuncAttributeMaxDynamicSharedMemorySize, SMEM_BYTES);

    // 1) x -> fp16 (octet-permuted)
    {
        int total = (int)(((size_t)TOKENS * IN_F) / 8);  // 4,194,304 octets
        xconv_kernel<<<total / 256, 256>>>(x);
    }
    // 2) warp-specialized fused dequant + GEMM + bias
    {
        dim3 grid(TOKENS / BM, OUT_F / BN);  // (64, 86)
        gemm_kernel<<<grid, NTHREADS, SMEM_BYTES>>>(qw, qz, sc, bias, out);
    }
}

// round 14
// speedup vs baseline: 1.2590x; 1.2590x over previous
#include <cuda_runtime.h>
#include <cuda_fp16.h>
#include <cstdint>
#include <cstddef>

// ---------------- problem constants ----------------
#define TOKENS 8192
#define IN_F   4096
#define OUT_F  11008

// ---------------- GEMM tiling ----------------
#define BM 128
#define BN 128
#define BK 64
#define STAGES 3
#define KITERS (IN_F / BK)          // 64
#define NTHREADS 128                // 4 warps, 2x2 grid, 64x64 warp tiles

// SMEM layout (byte offsets from 1024-aligned base)
#define OFF_A      0                         // 3 x 16384 (A fp16, SW128)
#define OFF_B      (OFF_A + STAGES * 16384)  // 3 x 16384 (B fp16, SW128)
#define SMEM_USED  (OFF_B + STAGES * 16384)  // 98304
#define SMEM_BYTES (SMEM_USED + 1024)        // 99328 -> 2 CTAs/SM

// ---------------- scratch (static device global; no allocation) ----------------
// x fp16, octet-permuted: pos p of each 8-k octet holds x[oct*8 + perm[p]],
// perm = [0,4,1,5,2,6,3,7]; B dequant emits the same permutation -> GEMM invariant.
__device__ __align__(1024) __half g_X[(size_t)TOKENS * IN_F]; // 67 MB

// ---------------- PTX helpers (baseline sm_80+ only) ----------------
__device__ __forceinline__ uint32_t smem_u32(const void* p) {
    uint32_t a;
    asm("{ .reg .u64 t; cvta.to.shared.u64 t, %1; cvt.u32.u64 %0, t; }" : "=r"(a) : "l"(p));
    return a;
}
__device__ __forceinline__ void cp_async16(uint32_t dst, const void* src) {
    asm volatile("cp.async.cg.shared.global [%0], [%1], 16;" :: "r"(dst), "l"(src) : "memory");
}
__device__ __forceinline__ void cp_commit() {
    asm volatile("cp.async.commit_group;" ::: "memory");
}
template <int N> __device__ __forceinline__ void cp_wait() {
    asm volatile("cp.async.wait_group %0;" :: "n"(N) : "memory");
}
__device__ __forceinline__ void ldsm_x4(uint32_t& r0, uint32_t& r1, uint32_t& r2, uint32_t& r3,
                                        uint32_t addr) {
    asm volatile("ldmatrix.sync.aligned.m8n8.x4.shared.b16 {%0,%1,%2,%3}, [%4];"
                 : "=r"(r0), "=r"(r1), "=r"(r2), "=r"(r3) : "r"(addr));
}
__device__ __forceinline__ void sts128(uint32_t addr, uint32_t r0, uint32_t r1,
                                       uint32_t r2, uint32_t r3) {
    asm volatile("st.shared.v4.b32 [%0], {%1,%2,%3,%4};"
                 :: "r"(addr), "r"(r0), "r"(r1), "r"(r2), "r"(r3) : "memory");
}
__device__ __forceinline__ void mma16816(float* c, const uint32_t* a, const uint32_t* b) {
    asm volatile(
        "mma.sync.aligned.m16n8k16.row.col.f32.f16.f16.f32 "
        "{%0,%1,%2,%3}, {%4,%5,%6,%7}, {%8,%9}, {%0,%1,%2,%3};"
        : "+f"(c[0]), "+f"(c[1]), "+f"(c[2]), "+f"(c[3])
        : "r"(a[0]), "r"(a[1]), "r"(a[2]), "r"(a[3]), "r"(b[0]), "r"(b[1]));
}

// SW128 swizzle on byte offset within a tile (128B rows)
#define SWZ(o) ((o) ^ (((o) >> 3) & 0x70))

// ---------------- kernel 1: x fp32 -> fp16, octet-permuted ----------------
__global__ void __launch_bounds__(256) xconv_kernel(const float* __restrict__ x) {
    size_t i = (size_t)blockIdx.x * blockDim.x + threadIdx.x;  // one octet each
    const float4* p = (const float4*)(x + i * 8);
    float4 v0 = p[0];
    float4 v1 = p[1];
    union { __half2 h[4]; uint4 u; } r;
    r.h[0] = __floats2half2_rn(v0.x, v1.x);
    r.h[1] = __floats2half2_rn(v0.y, v1.y);
    r.h[2] = __floats2half2_rn(v0.z, v1.z);
    r.h[3] = __floats2half2_rn(v0.w, v1.w);
    ((uint4*)g_X)[i] = r.u;
}

// ---------------- kernel 2: fused dequant + pipelined HMMA GEMM ----------------
// A tiles via cp.async (3-stage); raw qweight/scale/zero prefetched per thread
// into REGISTERS one iteration ahead (LDG, fully coalesced), so dequant is pure
// ALU+STS with no SMEM round-trip for the quantized data.
__device__ __forceinline__ void issue_A(int kt, uint32_t sb, const __half* gA, int tid) {
    const int s  = kt % STAGES;
    const int k0 = kt * BK;
    uint32_t aBase = sb + OFF_A + s * 16384;
#pragma unroll
    for (int it = 0; it < 8; ++it) {
        int chunk = tid + it * NTHREADS;
        int r = chunk >> 3, c = chunk & 7;
        cp_async16(aBase + SWZ((uint32_t)(r * 128 + c * 16)),
                   gA + (size_t)r * IN_F + k0 + c * 8);
    }
    cp_commit();
}

// dequant 8 register-resident raw words for stage kt -> B tile slot kt%STAGES
__device__ __forceinline__ void dequant_regs(int kt, uint32_t sb, const uint32_t* raw,
                                             __half2 s2, __half2 hz2, int n) {
    uint32_t bBase = sb + OFF_B + (kt % STAGES) * 16384;
#pragma unroll
    for (int kp = 0; kp < 8; ++kp) {
        uint32_t w = raw[kp];
        uint32_t q0 = (w & 0x000F000Fu) | 0x64006400u;
        uint32_t q1 = ((w >> 4)  & 0x000F000Fu) | 0x64006400u;
        uint32_t q2 = ((w >> 8)  & 0x000F000Fu) | 0x64006400u;
        uint32_t q3 = ((w >> 12) & 0x000F000Fu) | 0x64006400u;
        union { __half2 h; uint32_t u; } r0, r1, r2, r3;
        r0.h = __hmul2(__hsub2(*(__half2*)&q0, hz2), s2);
        r1.h = __hmul2(__hsub2(*(__half2*)&q1, hz2), s2);
        r2.h = __hmul2(__hsub2(*(__half2*)&q2, hz2), s2);
        r3.h = __hmul2(__hsub2(*(__half2*)&q3, hz2), s2);
        sts128(bBase + SWZ((uint32_t)(n * 128 + kp * 16)), r0.u, r1.u, r2.u, r3.u);
    }
}

__global__ void __launch_bounds__(NTHREADS, 2) gemm_kernel(const int* __restrict__ qw,
                                                           const int* __restrict__ qz,
                                                           const float* __restrict__ sc,
                                                           const float* __restrict__ bias,
                                                           float* __restrict__ out) {
    extern __shared__ char dynsmem_raw[];
    const int tid = threadIdx.x;
    const int wid = tid >> 5;
    const int lid = tid & 31;
    const int wm = wid & 1;       // 2 m-warps (64 rows each)
    const int wn = wid >> 1;      // 2 n-warps (64 cols each)
    const int m0 = blockIdx.x * BM;   // 64 m-tiles
    const int n0 = blockIdx.y * BN;   // 86 n-tiles

    uint32_t sb0 = smem_u32(dynsmem_raw);
    uint32_t sb  = (sb0 + 1023) & ~1023u;            // 1024-aligned base

    const __half* gA = g_X + (size_t)m0 * IN_F;

    float acc[4][8][4];
#pragma unroll
    for (int mi = 0; mi < 4; ++mi)
#pragma unroll
        for (int ni = 0; ni < 8; ++ni)
#pragma unroll
            for (int q = 0; q < 4; ++q) acc[mi][ni][q] = 0.0f;

    // per-lane ldmatrix components
    const int aRow = wm * 64 + (lid & 15);            // + mi*16
    const int aChk = lid >> 4;                        // + 2*kk
    const int bRow = wn * 64 + (lid & 7) + ((lid >> 4) & 1) * 8;  // + nj*16
    const int bChk = (lid >> 3) & 1;                  // + 2*kk
    const int n = tid;                                // dequant column ownership
    const int zsh = (n & 7) * 4;

    // per-thread global pointers (column n0+n)
    const int*   qwp = qw + n0 + n;                   // + (k/8)*OUT_F
    const float* scp = sc + n0 + n;                   // + g*OUT_F
    const int*   qzp = qz + ((n0 + n) >> 3);          // + g*(OUT_F/8)

    // prefetch registers for stage j+1's dequant
    uint32_t rawreg[8];
    __half2 s2, hz2;

    // ---- prologue ----
    issue_A(0, sb, gA, tid);
    issue_A(1, sb, gA, tid);
    issue_A(2, sb, gA, tid);
    {
        // stage 0 raw -> regs (LDG), dequant into B slot 0
#pragma unroll
        for (int kp = 0; kp < 8; ++kp)
            rawreg[kp] = (uint32_t)__ldg(qwp + (size_t)kp * OUT_F);
        float sf = __ldg(scp);
        int   z  = (int)(((uint32_t)__ldg(qzp) >> zsh) & 15u);
        __half2 s20  = __float2half2_rn(sf);
        __half2 hz20 = __float2half2_rn(1024.0f + (float)z);
        cp_wait<2>();                 // A(0) landed
        dequant_regs(0, sb, rawreg, s20, hz20, n);
    }
    __syncthreads();                  // A(0), B(0) visible to all

    for (int j = 0; j < KITERS; ++j) {
        // ---- prefetch raw(j+1) into registers (consumed after MMA below) ----
        if (j + 1 < KITERS) {
            const int k1 = (j + 1) * 8;           // packed-k base row
            const int g1 = ((j + 1) * BK) >> 7;
#pragma unroll
            for (int kp = 0; kp < 8; ++kp)
                rawreg[kp] = (uint32_t)__ldg(qwp + (size_t)(k1 + kp) * OUT_F);
            float sf = __ldg(scp + (size_t)g1 * OUT_F);
            int   z  = (int)(((uint32_t)__ldg(qzp + (size_t)g1 * (OUT_F / 8)) >> zsh) & 15u);
            s2  = __float2half2_rn(sf);
            hz2 = __float2half2_rn(1024.0f + (float)z);
        }

        // ---- MMA on stage j (A(j), B(j) visible since last barrier) ----
        const uint32_t aT = sb + OFF_A + (j % STAGES) * 16384;
        const uint32_t bT = sb + OFF_B + (j % STAGES) * 16384;
#pragma unroll
        for (int kk = 0; kk < BK / 16; ++kk) {
            uint32_t a[4][4];
#pragma unroll
            for (int mi = 0; mi < 4; ++mi) {
                uint32_t ad = aT + SWZ((uint32_t)((aRow + mi * 16) * 128 + (2 * kk + aChk) * 16));
                ldsm_x4(a[mi][0], a[mi][1], a[mi][2], a[mi][3], ad);
            }
            uint32_t b[8][2];
#pragma unroll
            for (int nj = 0; nj < 4; ++nj) {
                uint32_t bd = bT + SWZ((uint32_t)((bRow + nj * 16) * 128 + (2 * kk + bChk) * 16));
                uint32_t r0, r1, r2, r3;
                ldsm_x4(r0, r1, r2, r3, bd);
                b[2 * nj][0] = r0;     b[2 * nj][1] = r1;
                b[2 * nj + 1][0] = r2; b[2 * nj + 1][1] = r3;
            }
#pragma unroll
            for (int mi = 0; mi < 4; ++mi)
#pragma unroll
                for (int ni = 0; ni < 8; ++ni)
                    mma16816(acc[mi][ni], a[mi], b[ni]);
        }

        // ---- prepare stage j+1: dequant from registers (no LDS) ----
        if (j + 1 < KITERS) {
            if (j + 2 < KITERS) cp_wait<1>();   // A(j+1) landed
            else                cp_wait<0>();
            dequant_regs(j + 1, sb, rawreg, s2, hz2, n);  // writes B slot (j+1)%3
            __syncthreads();  // publishes B(j+1)/A(j+1); all MMA(j) reads done
            if (j + 3 < KITERS)
                issue_A(j + 3, sb, gA, tid);    // reuses A slot j%3 safely
        }
    }

    // ---- epilogue: direct stores with bias ----
    const int mw = m0 + wm * 64;
    const int nw = n0 + wn * 64;
    const int rsub = lid >> 2;
    const int csub = (lid & 3) * 2;
#pragma unroll
    for (int mi = 0; mi < 4; ++mi) {
#pragma unroll
        for (int ni = 0; ni < 8; ++ni) {
            int col = nw + ni * 8 + csub;
            float2 bv = *(const float2*)(bias + col);
            int r0 = mw + mi * 16 + rsub;
            float2 v0 = { acc[mi][ni][0] + bv.x, acc[mi][ni][1] + bv.y };
            *(float2*)(out + (size_t)r0 * OUT_F + col) = v0;
            float2 v1 = { acc[mi][ni][2] + bv.x, acc[mi][ni][3] + bv.y };
            *(float2*)(out + (size_t)(r0 + 8) * OUT_F + col) = v1;
        }
    }
}

// ---------------- launch ----------------
extern "C" void kernel_launch(void* const* d_in, const int* in_sizes, int n_in,
                              void* d_out, int out_size) {
    const float* x    = (const float*)d_in[0];
    const int*   qw   = (const int*)d_in[1];
    const int*   qz   = (const int*)d_in[2];
    const float* sc   = (const float*)d_in[3];
    const float* bias = (const float*)d_in[4];
    float* out = (float*)d_out;

    cudaFuncSetAttribute(gemm_kernel, cudaFuncAttributeMaxDynamicSharedMemorySize, SMEM_BYTES);

    // 1) x -> fp16 (octet-permuted)
    {
        int total = (int)(((size_t)TOKENS * IN_F) / 8);  // 4,194,304 octets
        xconv_kernel<<<total / 256, 256>>>(x);
    }
    // 2) fused dequant + GEMM + bias
    {
        dim3 grid(TOKENS / BM, OUT_F / BN);  // (64, 86)
        gemm_kernel<<<grid, NTHREADS, SMEM_BYTES>>>(qw, qz, sc, bias, out);
    }
}

// round 16
// speedup vs baseline: 1.3730x; 1.0905x over previous
#include <cuda_runtime.h>
#include <cuda_fp16.h>
#include <cstdint>
#include <cstddef>

// ---------------- problem constants ----------------
#define TOKENS 8192
#define IN_F   4096
#define OUT_F  11008

// ---------------- GEMM tiling ----------------
#define BM 128
#define BN 128
#define BK 64
#define STAGES 3
#define KITERS (IN_F / BK)          // 64
#define NTHREADS 128                // 4 warps, 2x2 grid, 64x64 warp tiles

// SMEM layout (byte offsets from 1024-aligned base)
#define OFF_A      0                         // 3 x 16384 (A fp16, SW128)
#define OFF_B      (OFF_A + STAGES * 16384)  // 3 x 16384 (B fp16, SW128)
#define OFF_RAW    (OFF_B + STAGES * 16384)  // 3 x 4096  (raw[kp*128+n])
#define OFF_SC     (OFF_RAW + STAGES * 4096) // 3 x 512   (scale fp32 per n)
#define OFF_QZ     (OFF_SC + STAGES * 512)   // 3 x 512   (qz word per n)
#define SMEM_USED  (OFF_QZ + STAGES * 512)   // 113664
#define SMEM_BYTES (SMEM_USED + 1024)        // 114688 -> 2 CTAs/SM

// ---------------- scratch (static device global; no allocation) ----------------
// x fp16, octet-permuted: pos p of each 8-k octet holds x[oct*8 + perm[p]],
// perm = [0,4,1,5,2,6,3,7]; B dequant emits the same permutation -> GEMM invariant.
__device__ __align__(1024) __half g_X[(size_t)TOKENS * IN_F]; // 67 MB

// ---------------- PTX helpers (baseline sm_80+ only) ----------------
__device__ __forceinline__ uint32_t smem_u32(const void* p) {
    uint32_t a;
    asm("{ .reg .u64 t; cvta.to.shared.u64 t, %1; cvt.u32.u64 %0, t; }" : "=r"(a) : "l"(p));
    return a;
}
__device__ __forceinline__ void cp_async16(uint32_t dst, const void* src) {
    asm volatile("cp.async.cg.shared.global [%0], [%1], 16;" :: "r"(dst), "l"(src) : "memory");
}
__device__ __forceinline__ void cp_async4(uint32_t dst, const void* src) {
    asm volatile("cp.async.ca.shared.global [%0], [%1], 4;" :: "r"(dst), "l"(src) : "memory");
}
__device__ __forceinline__ void cp_commit() {
    asm volatile("cp.async.commit_group;" ::: "memory");
}
template <int N> __device__ __forceinline__ void cp_wait() {
    asm volatile("cp.async.wait_group %0;" :: "n"(N) : "memory");
}
__device__ __forceinline__ void ldsm_x4(uint32_t& r0, uint32_t& r1, uint32_t& r2, uint32_t& r3,
                                        uint32_t addr) {
    asm volatile("ldmatrix.sync.aligned.m8n8.x4.shared.b16 {%0,%1,%2,%3}, [%4];"
                 : "=r"(r0), "=r"(r1), "=r"(r2), "=r"(r3) : "r"(addr));
}
__device__ __forceinline__ void sts128(uint32_t addr, uint32_t r0, uint32_t r1,
                                       uint32_t r2, uint32_t r3) {
    asm volatile("st.shared.v4.b32 [%0], {%1,%2,%3,%4};"
                 :: "r"(addr), "r"(r0), "r"(r1), "r"(r2), "r"(r3) : "memory");
}
__device__ __forceinline__ uint32_t lds32(uint32_t addr) {
    uint32_t v;
    asm volatile("ld.shared.b32 %0, [%1];" : "=r"(v) : "r"(addr));
    return v;
}
__device__ __forceinline__ void mma16816(float* c, const uint32_t* a, const uint32_t* b) {
    asm volatile(
        "mma.sync.aligned.m16n8k16.row.col.f32.f16.f16.f32 "
        "{%0,%1,%2,%3}, {%4,%5,%6,%7}, {%8,%9}, {%0,%1,%2,%3};"
        : "+f"(c[0]), "+f"(c[1]), "+f"(c[2]), "+f"(c[3])
        : "r"(a[0]), "r"(a[1]), "r"(a[2]), "r"(a[3]), "r"(b[0]), "r"(b[1]));
}

// SW128 swizzle on byte offset within a tile (128B rows)
#define SWZ(o) ((o) ^ (((o) >> 3) & 0x70))

// ---------------- kernel 1: x fp32 -> fp16, octet-permuted ----------------
__global__ void __launch_bounds__(256) xconv_kernel(const float* __restrict__ x) {
    size_t i = (size_t)blockIdx.x * blockDim.x + threadIdx.x;  // one octet each
    const float4* p = (const float4*)(x + i * 8);
    float4 v0 = p[0];
    float4 v1 = p[1];
    union { __half2 h[4]; uint4 u; } r;
    r.h[0] = __floats2half2_rn(v0.x, v1.x);
    r.h[1] = __floats2half2_rn(v0.y, v1.y);
    r.h[2] = __floats2half2_rn(v0.z, v1.z);
    r.h[3] = __floats2half2_rn(v0.w, v1.w);
    ((uint4*)g_X)[i] = r.u;
}

// ---------------- kernel 2: fused dequant + pipelined HMMA GEMM ----------------
__device__ __forceinline__ void issue_group(int kt, uint32_t sb, const __half* gA,
                                            const int* qw, const int* qz,
                                            const float* sc, int n0, int tid) {
    const int s  = kt % STAGES;
    const int k0 = kt * BK;
    const int g  = k0 >> 7;          // quant group (BK=64 inside one 128-group)
    uint32_t aBase = sb + OFF_A + s * 16384;
#pragma unroll
    for (int it = 0; it < 8; ++it) {
        int chunk = tid + it * NTHREADS;
        int r = chunk >> 3, c = chunk & 7;
        cp_async16(aBase + SWZ((uint32_t)(r * 128 + c * 16)),
                   gA + (size_t)r * IN_F + k0 + c * 8);
    }
    // raw qweight: thread t owns column n0+t -> 8 words (coalesced per warp)
    const int n = tid;
    uint32_t rawBase = sb + OFF_RAW + s * 4096;
#pragma unroll
    for (int kp = 0; kp < 8; ++kp)
        cp_async4(rawBase + (uint32_t)(kp * 512 + n * 4),
                  qw + (size_t)(k0 / 8 + kp) * OUT_F + n0 + n);
    cp_async4(sb + OFF_SC + s * 512 + n * 4, sc + (size_t)g * OUT_F + n0 + n);
    cp_async4(sb + OFF_QZ + s * 512 + n * 4, qz + (size_t)g * (OUT_F / 8) + ((n0 + n) >> 3));
    cp_commit();
}

// Dequant stage kt (pure ALU+STS; raw loads batched; s2/hz2 precomputed).
__device__ __forceinline__ void dequant_stage(int kt, uint32_t sb, int tid,
                                              __half2 s2, __half2 hz2) {
    const int s = kt % STAGES;
    const uint32_t rawB = sb + OFF_RAW + s * 4096;
    uint32_t bBase = sb + OFF_B + s * 16384;
    const int n = tid;  // 0..127

    // batched loads: 8 independent LDS issued back-to-back
    uint32_t w[8];
#pragma unroll
    for (int kp = 0; kp < 8; ++kp)
        w[kp] = lds32(rawB + (uint32_t)(kp * 512 + n * 4));

#pragma unroll
    for (int kp = 0; kp < 8; ++kp) {
        uint32_t q0 = (w[kp] & 0x000F000Fu) | 0x64006400u;
        uint32_t q1 = ((w[kp] >> 4)  & 0x000F000Fu) | 0x64006400u;
        uint32_t q2 = ((w[kp] >> 8)  & 0x000F000Fu) | 0x64006400u;
        uint32_t q3 = ((w[kp] >> 12) & 0x000F000Fu) | 0x64006400u;
        union { __half2 h; uint32_t u; } r0, r1, r2, r3;
        r0.h = __hmul2(__hsub2(*(__half2*)&q0, hz2), s2);
        r1.h = __hmul2(__hsub2(*(__half2*)&q1, hz2), s2);
        r2.h = __hmul2(__hsub2(*(__half2*)&q2, hz2), s2);
        r3.h = __hmul2(__hsub2(*(__half2*)&q3, hz2), s2);
        sts128(bBase + SWZ((uint32_t)(n * 128 + kp * 16)), r0.u, r1.u, r2.u, r3.u);
    }
}

__global__ void __launch_bounds__(NTHREADS, 2) gemm_kernel(const int* __restrict__ qw,
                                                           const int* __restrict__ qz,
                                                           const float* __restrict__ sc,
                                                           const float* __restrict__ bias,
                                                           float* __restrict__ out) {
    extern __shared__ char dynsmem_raw[];
    const int tid = threadIdx.x;
    const int wid = tid >> 5;
    const int lid = tid & 31;
    const int wm = wid & 1;       // 2 m-warps (64 rows each)
    const int wn = wid >> 1;      // 2 n-warps (64 cols each)
    const int m0 = blockIdx.x * BM;   // 64 m-tiles
    const int n0 = blockIdx.y * BN;   // 86 n-tiles

    uint32_t sb0 = smem_u32(dynsmem_raw);
    uint32_t sb  = (sb0 + 1023) & ~1023u;            // 1024-aligned base

    const __half* gA = g_X + (size_t)m0 * IN_F;

    float acc[4][8][4];
#pragma unroll
    for (int mi = 0; mi < 4; ++mi)
#pragma unroll
        for (int ni = 0; ni < 8; ++ni)
#pragma unroll
            for (int q = 0; q < 4; ++q) acc[mi][ni][q] = 0.0f;

    // per-lane ldmatrix components
    const int aRow = wm * 64 + (lid & 15);            // + mi*16
    const int aChk = lid >> 4;                        // + 2*kk
    const int bRow = wn * 64 + (lid & 7) + ((lid >> 4) & 1) * 8;  // + nj*16
    const int bChk = (lid >> 3) & 1;                  // + 2*kk
    const int n = tid;                                // dequant column ownership
    const int zsh = (n & 7) * 4;

    // ---- prologue ----
    issue_group(0, sb, gA, qw, qz, sc, n0, tid);
    issue_group(1, sb, gA, qw, qz, sc, n0, tid);
    issue_group(2, sb, gA, qw, qz, sc, n0, tid);
    cp_wait<2>();            // stage 0 landed (self-visible)
    {
        float sf = __uint_as_float(lds32(sb + OFF_SC + n * 4));
        int   z  = (int)((lds32(sb + OFF_QZ + n * 4) >> zsh) & 15u);
        dequant_stage(0, sb, tid, __float2half2_rn(sf),
                      __float2half2_rn(1024.0f + (float)z));
    }
    __syncthreads();         // A(0), B(0) visible to all

    for (int j = 0; j < KITERS; ++j) {
        // ---- hoisted: group j+1 sync + scale/zero prep (hidden under MMA) ----
        __half2 s2, hz2;
        if (j + 1 < KITERS) {
            if (j + 2 < KITERS) cp_wait<1>();   // group j+1 landed (long ago)
            else                cp_wait<0>();
            const int s1 = (j + 1) % STAGES;
            float sf = __uint_as_float(lds32(sb + OFF_SC + s1 * 512 + n * 4));
            int   z  = (int)((lds32(sb + OFF_QZ + s1 * 512 + n * 4) >> zsh) & 15u);
            s2  = __float2half2_rn(sf);
            hz2 = __float2half2_rn(1024.0f + (float)z);
        }

        // ---- MMA on stage j (A(j), B(j) visible since last barrier) ----
        const uint32_t aT = sb + OFF_A + (j % STAGES) * 16384;
        const uint32_t bT = sb + OFF_B + (j % STAGES) * 16384;
#pragma unroll
        for (int kk = 0; kk < BK / 16; ++kk) {
            uint32_t a[4][4];
#pragma unroll
            for (int mi = 0; mi < 4; ++mi) {
                uint32_t ad = aT + SWZ((uint32_t)((aRow + mi * 16) * 128 + (2 * kk + aChk) * 16));
                ldsm_x4(a[mi][0], a[mi][1], a[mi][2], a[mi][3], ad);
            }
            uint32_t b[8][2];
#pragma unroll
            for (int nj = 0; nj < 4; ++nj) {
                uint32_t bd = bT + SWZ((uint32_t)((bRow + nj * 16) * 128 + (2 * kk + bChk) * 16));
                uint32_t r0, r1, r2, r3;
                ldsm_x4(r0, r1, r2, r3, bd);
                b[2 * nj][0] = r0;     b[2 * nj][1] = r1;
                b[2 * nj + 1][0] = r2; b[2 * nj + 1][1] = r3;
            }
#pragma unroll
            for (int mi = 0; mi < 4; ++mi)
#pragma unroll
                for (int ni = 0; ni < 8; ++ni)
                    mma16816(acc[mi][ni], a[mi], b[ni]);
        }

        // ---- tail: dequant (batched LDS, precomputed scales), publish, refill ----
        if (j + 1 < KITERS) {
            dequant_stage(j + 1, sb, tid, s2, hz2);  // writes B slot (j+1)%3
            __syncthreads();  // publishes B(j+1)/A(j+1); all MMA(j) reads done
            if (j + 3 < KITERS)
                issue_group(j + 3, sb, gA, qw, qz, sc, n0, tid);  // reuses slot j%3 safely
        }
    }

    // ---- epilogue: direct stores with bias ----
    const int mw = m0 + wm * 64;
    const int nw = n0 + wn * 64;
    const int rsub = lid >> 2;
    const int csub = (lid & 3) * 2;
#pragma unroll
    for (int mi = 0; mi < 4; ++mi) {
#pragma unroll
        for (int ni = 0; ni < 8; ++ni) {
            int col = nw + ni * 8 + csub;
            float2 bv = *(const float2*)(bias + col);
            int r0 = mw + mi * 16 + rsub;
            float2 v0 = { acc[mi][ni][0] + bv.x, acc[mi][ni][1] + bv.y };
            *(float2*)(out + (size_t)r0 * OUT_F + col) = v0;
            float2 v1 = { acc[mi][ni][2] + bv.x, acc[mi][ni][3] + bv.y };
            *(float2*)(out + (size_t)(r0 + 8) * OUT_F + col) = v1;
        }
    }
}

// ---------------- launch ----------------
extern "C" void kernel_launch(void* const* d_in, const int* in_sizes, int n_in,
                              void* d_out, int out_size) {
    const float* x    = (const float*)d_in[0];
    const int*   qw   = (const int*)d_in[1];
    const int*   qz   = (const int*)d_in[2];
    const float* sc   = (const float*)d_in[3];
    const float* bias = (const float*)d_in[4];
    float* out = (float*)d_out;

    cudaFuncSetAttribute(gemm_kernel, cudaFuncAttributeMaxDynamicSharedMemorySize, SMEM_BYTES);

    // 1) x -> fp16 (octet-permuted)
    {
        int total = (int)(((size_t)TOKENS * IN_F) / 8);  // 4,194,304 octets
        xconv_kernel<<<total / 256, 256>>>(x);
    }
    // 2) fused dequant + GEMM + bias
    {
        dim3 grid(TOKENS / BM, OUT_F / BN);  // (64, 86)
        gemm_kernel<<<grid, NTHREADS, SMEM_BYTES>>>(qw, qz, sc, bias, out);
    }
}

// round 17
// speedup vs baseline: 1.3837x; 1.0078x over previous
#include <cuda_runtime.h>
#include <cuda_fp16.h>
#include <cstdint>
#include <cstddef>

// ---------------- problem constants ----------------
#define TOKENS 8192
#define IN_F   4096
#define OUT_F  11008

// ---------------- GEMM tiling ----------------
#define BM 128
#define BN 128
#define BK 64
#define STAGES 3
#define KITERS (IN_F / BK)          // 64
#define NTHREADS 128                // 4 warps, 2x2 grid, 64x64 warp tiles

// SMEM layout (byte offsets from 1024-aligned base)
#define OFF_A      0                         // 3 x 16384 (A fp16, SW128)
#define OFF_B      (OFF_A + STAGES * 16384)  // 3 x 16384 (B fp16, SW128)
#define OFF_RAW    (OFF_B + STAGES * 16384)  // 3 x 4096  (raw[kp*128+n])
#define OFF_SC     (OFF_RAW + STAGES * 4096) // 3 x 512   (scale fp32 per n)
#define OFF_QZ     (OFF_SC + STAGES * 512)   // 3 x 512   (qz word per n)
#define SMEM_USED  (OFF_QZ + STAGES * 512)   // 113664
#define SMEM_BYTES (SMEM_USED + 1024)        // 114688 -> 2 CTAs/SM

// ---------------- scratch (static device global; no allocation) ----------------
// x fp16, octet-permuted: pos p of each 8-k octet holds x[oct*8 + perm[p]],
// perm = [0,4,1,5,2,6,3,7]; B dequant emits the same permutation -> GEMM invariant.
__device__ __align__(1024) __half g_X[(size_t)TOKENS * IN_F]; // 67 MB

// ---------------- PTX helpers (baseline sm_80+ only) ----------------
__device__ __forceinline__ uint32_t smem_u32(const void* p) {
    uint32_t a;
    asm("{ .reg .u64 t; cvta.to.shared.u64 t, %1; cvt.u32.u64 %0, t; }" : "=r"(a) : "l"(p));
    return a;
}
__device__ __forceinline__ void cp_async16(uint32_t dst, const void* src) {
    asm volatile("cp.async.cg.shared.global [%0], [%1], 16;" :: "r"(dst), "l"(src) : "memory");
}
__device__ __forceinline__ void cp_async4(uint32_t dst, const void* src) {
    asm volatile("cp.async.ca.shared.global [%0], [%1], 4;" :: "r"(dst), "l"(src) : "memory");
}
__device__ __forceinline__ void cp_commit() {
    asm volatile("cp.async.commit_group;" ::: "memory");
}
template <int N> __device__ __forceinline__ void cp_wait() {
    asm volatile("cp.async.wait_group %0;" :: "n"(N) : "memory");
}
__device__ __forceinline__ void ldsm_x4(uint32_t& r0, uint32_t& r1, uint32_t& r2, uint32_t& r3,
                                        uint32_t addr) {
    asm volatile("ldmatrix.sync.aligned.m8n8.x4.shared.b16 {%0,%1,%2,%3}, [%4];"
                 : "=r"(r0), "=r"(r1), "=r"(r2), "=r"(r3) : "r"(addr));
}
__device__ __forceinline__ void sts128(uint32_t addr, uint32_t r0, uint32_t r1,
                                       uint32_t r2, uint32_t r3) {
    asm volatile("st.shared.v4.b32 [%0], {%1,%2,%3,%4};"
                 :: "r"(addr), "r"(r0), "r"(r1), "r"(r2), "r"(r3) : "memory");
}
__device__ __forceinline__ uint32_t lds32(uint32_t addr) {
    uint32_t v;
    asm volatile("ld.shared.b32 %0, [%1];" : "=r"(v) : "r"(addr));
    return v;
}
__device__ __forceinline__ void mma16816(float* c, const uint32_t* a, const uint32_t* b) {
    asm volatile(
        "mma.sync.aligned.m16n8k16.row.col.f32.f16.f16.f32 "
        "{%0,%1,%2,%3}, {%4,%5,%6,%7}, {%8,%9}, {%0,%1,%2,%3};"
        : "+f"(c[0]), "+f"(c[1]), "+f"(c[2]), "+f"(c[3])
        : "r"(a[0]), "r"(a[1]), "r"(a[2]), "r"(a[3]), "r"(b[0]), "r"(b[1]));
}

// SW128 swizzle on byte offset within a tile (128B rows)
#define SWZ(o) ((o) ^ (((o) >> 3) & 0x70))

// ---------------- kernel 1: x fp32 -> fp16, octet-permuted ----------------
__global__ void __launch_bounds__(256) xconv_kernel(const float* __restrict__ x) {
    size_t i = (size_t)blockIdx.x * blockDim.x + threadIdx.x;  // one octet each
    const float4* p = (const float4*)(x + i * 8);
    float4 v0 = p[0];
    float4 v1 = p[1];
    union { __half2 h[4]; uint4 u; } r;
    r.h[0] = __floats2half2_rn(v0.x, v1.x);
    r.h[1] = __floats2half2_rn(v0.y, v1.y);
    r.h[2] = __floats2half2_rn(v0.z, v1.z);
    r.h[3] = __floats2half2_rn(v0.w, v1.w);
    ((uint4*)g_X)[i] = r.u;
}

// ---------------- kernel 2: fused dequant + pipelined HMMA GEMM ----------------
// One quarter of the cp.async issue work for stage kt (called at kk=0..3 inside
// the MMA loop of iteration kt-2, so issue cost hides in MMA slack; no commit).
__device__ __forceinline__ void issue_part(int kt, int part, uint32_t sb,
                                           const __half* gA, const int* qw,
                                           const int* qz, const float* sc,
                                           int n0, int tid) {
    const int s  = kt % STAGES;
    const int k0 = kt * BK;
    uint32_t aBase = sb + OFF_A + s * 16384;
#pragma unroll
    for (int it = 2 * part; it < 2 * part + 2; ++it) {
        int chunk = tid + it * NTHREADS;
        int r = chunk >> 3, c = chunk & 7;
        cp_async16(aBase + SWZ((uint32_t)(r * 128 + c * 16)),
                   gA + (size_t)r * IN_F + k0 + c * 8);
    }
    const int n = tid;
    uint32_t rawBase = sb + OFF_RAW + s * 4096;
#pragma unroll
    for (int kp = 2 * part; kp < 2 * part + 2; ++kp)
        cp_async4(rawBase + (uint32_t)(kp * 512 + n * 4),
                  qw + (size_t)(k0 / 8 + kp) * OUT_F + n0 + n);
    if (part == 0) {
        const int g = k0 >> 7;
        cp_async4(sb + OFF_SC + s * 512 + n * 4, sc + (size_t)g * OUT_F + n0 + n);
        cp_async4(sb + OFF_QZ + s * 512 + n * 4, qz + (size_t)g * (OUT_F / 8) + ((n0 + n) >> 3));
    }
}

// Dequant stage kt (batched LDS, then pure ALU+STS; s2/hz2 precomputed).
__device__ __forceinline__ void dequant_stage(int kt, uint32_t sb, int tid,
                                              __half2 s2, __half2 hz2) {
    const int s = kt % STAGES;
    const uint32_t rawB = sb + OFF_RAW + s * 4096;
    uint32_t bBase = sb + OFF_B + s * 16384;
    const int n = tid;  // 0..127

    uint32_t w[8];
#pragma unroll
    for (int kp = 0; kp < 8; ++kp)
        w[kp] = lds32(rawB + (uint32_t)(kp * 512 + n * 4));

#pragma unroll
    for (int kp = 0; kp < 8; ++kp) {
        uint32_t q0 = (w[kp] & 0x000F000Fu) | 0x64006400u;
        uint32_t q1 = ((w[kp] >> 4)  & 0x000F000Fu) | 0x64006400u;
        uint32_t q2 = ((w[kp] >> 8)  & 0x000F000Fu) | 0x64006400u;
        uint32_t q3 = ((w[kp] >> 12) & 0x000F000Fu) | 0x64006400u;
        union { __half2 h; uint32_t u; } r0, r1, r2, r3;
        r0.h = __hmul2(__hsub2(*(__half2*)&q0, hz2), s2);
        r1.h = __hmul2(__hsub2(*(__half2*)&q1, hz2), s2);
        r2.h = __hmul2(__hsub2(*(__half2*)&q2, hz2), s2);
        r3.h = __hmul2(__hsub2(*(__half2*)&q3, hz2), s2);
        sts128(bBase + SWZ((uint32_t)(n * 128 + kp * 16)), r0.u, r1.u, r2.u, r3.u);
    }
}

__global__ void __launch_bounds__(NTHREADS, 2) gemm_kernel(const int* __restrict__ qw,
                                                           const int* __restrict__ qz,
                                                           const float* __restrict__ sc,
                                                           const float* __restrict__ bias,
                                                           float* __restrict__ out) {
    extern __shared__ char dynsmem_raw[];
    const int tid = threadIdx.x;
    const int wid = tid >> 5;
    const int lid = tid & 31;
    const int wm = wid & 1;       // 2 m-warps (64 rows each)
    const int wn = wid >> 1;      // 2 n-warps (64 cols each)
    const int m0 = blockIdx.x * BM;   // 64 m-tiles
    const int n0 = blockIdx.y * BN;   // 86 n-tiles

    uint32_t sb0 = smem_u32(dynsmem_raw);
    uint32_t sb  = (sb0 + 1023) & ~1023u;            // 1024-aligned base

    const __half* gA = g_X + (size_t)m0 * IN_F;

    float acc[4][8][4];
#pragma unroll
    for (int mi = 0; mi < 4; ++mi)
#pragma unroll
        for (int ni = 0; ni < 8; ++ni)
#pragma unroll
            for (int q = 0; q < 4; ++q) acc[mi][ni][q] = 0.0f;

    // per-lane ldmatrix components
    const int aRow = wm * 64 + (lid & 15);            // + mi*16
    const int aChk = lid >> 4;                        // + 2*kk
    const int bRow = wn * 64 + (lid & 7) + ((lid >> 4) & 1) * 8;  // + nj*16
    const int bChk = (lid >> 3) & 1;                  // + 2*kk
    const int n = tid;                                // dequant column ownership
    const int zsh = (n & 7) * 4;

    // ---- prologue: full groups for stages 0 and 1 ----
#pragma unroll
    for (int p = 0; p < 4; ++p) issue_part(0, p, sb, gA, qw, qz, sc, n0, tid);
    cp_commit();
#pragma unroll
    for (int p = 0; p < 4; ++p) issue_part(1, p, sb, gA, qw, qz, sc, n0, tid);
    cp_commit();
    cp_wait<1>();            // group 0 landed (self-visible)
    {
        float sf = __uint_as_float(lds32(sb + OFF_SC + n * 4));
        int   z  = (int)((lds32(sb + OFF_QZ + n * 4) >> zsh) & 15u);
        dequant_stage(0, sb, tid, __float2half2_rn(sf),
                      __float2half2_rn(1024.0f + (float)z));
    }
    __syncthreads();         // A(0), B(0) visible to all

    for (int j = 0; j < KITERS; ++j) {
        const bool do_issue = (j + 2 < KITERS);

        // ---- MMA on stage j, with stage j+2's cp.async issue spread across kk ----
        const uint32_t aT = sb + OFF_A + (j % STAGES) * 16384;
        const uint32_t bT = sb + OFF_B + (j % STAGES) * 16384;
#pragma unroll
        for (int kk = 0; kk < BK / 16; ++kk) {
            uint32_t a[4][4];
#pragma unroll
            for (int mi = 0; mi < 4; ++mi) {
                uint32_t ad = aT + SWZ((uint32_t)((aRow + mi * 16) * 128 + (2 * kk + aChk) * 16));
                ldsm_x4(a[mi][0], a[mi][1], a[mi][2], a[mi][3], ad);
            }
            uint32_t b[8][2];
#pragma unroll
            for (int nj = 0; nj < 4; ++nj) {
                uint32_t bd = bT + SWZ((uint32_t)((bRow + nj * 16) * 128 + (2 * kk + bChk) * 16));
                uint32_t r0, r1, r2, r3;
                ldsm_x4(r0, r1, r2, r3, bd);
                b[2 * nj][0] = r0;     b[2 * nj][1] = r1;
                b[2 * nj + 1][0] = r2; b[2 * nj + 1][1] = r3;
            }
            if (do_issue)   // fire-and-forget; A slot (j+2)%3 freed at barrier j-1
                issue_part(j + 2, kk, sb, gA, qw, qz, sc, n0, tid);
#pragma unroll
            for (int mi = 0; mi < 4; ++mi)
#pragma unroll
                for (int ni = 0; ni < 8; ++ni)
                    mma16816(acc[mi][ni], a[mi], b[ni]);
        }
        if (do_issue) cp_commit();   // group(j+2) committed

        // ---- tail: wait group j+1, dequant, publish ----
        if (j + 1 < KITERS) {
            if (do_issue) cp_wait<1>();   // pending {j+1, j+2}: wait j+1
            else          cp_wait<0>();   // pending {j+1}
            const int s1 = (j + 1) % STAGES;
            float sf = __uint_as_float(lds32(sb + OFF_SC + s1 * 512 + n * 4));
            int   z  = (int)((lds32(sb + OFF_QZ + s1 * 512 + n * 4) >> zsh) & 15u);
            dequant_stage(j + 1, sb, tid, __float2half2_rn(sf),
                          __float2half2_rn(1024.0f + (float)z));
            __syncthreads();  // publishes B(j+1)/A(j+1); frees A/B slot j%3
        }
    }

    // ---- epilogue: direct stores with bias ----
    const int mw = m0 + wm * 64;
    const int nw = n0 + wn * 64;
    const int rsub = lid >> 2;
    const int csub = (lid & 3) * 2;
#pragma unroll
    for (int mi = 0; mi < 4; ++mi) {
#pragma unroll
        for (int ni = 0; ni < 8; ++ni) {
            int col = nw + ni * 8 + csub;
            float2 bv = *(const float2*)(bias + col);
            int r0 = mw + mi * 16 + rsub;
            float2 v0 = { acc[mi][ni][0] + bv.x, acc[mi][ni][1] + bv.y };
            *(float2*)(out + (size_t)r0 * OUT_F + col) = v0;
            float2 v1 = { acc[mi][ni][2] + bv.x, acc[mi][ni][3] + bv.y };
            *(float2*)(out + (size_t)(r0 + 8) * OUT_F + col) = v1;
        }
    }
}

// ---------------- launch ----------------
extern "C" void kernel_launch(void* const* d_in, const int* in_sizes, int n_in,
                              void* d_out, int out_size) {
    const float* x    = (const float*)d_in[0];
    const int*   qw   = (const int*)d_in[1];
    const int*   qz   = (const int*)d_in[2];
    const float* sc   = (const float*)d_in[3];
    const float* bias = (const float*)d_in[4];
    float* out = (float*)d_out;

    cudaFuncSetAttribute(gemm_kernel, cudaFuncAttributeMaxDynamicSharedMemorySize, SMEM_BYTES);

    // 1) x -> fp16 (octet-permuted)
    {
        int total = (int)(((size_t)TOKENS * IN_F) / 8);  // 4,194,304 octets
        xconv_kernel<<<total / 256, 256>>>(x);
    }
    // 2) fused dequant + GEMM + bias
    {
        dim3 grid(TOKENS / BM, OUT_F / BN);  // (64, 86)
        gemm_kernel<<<grid, NTHREADS, SMEM_BYTES>>>(qw, qz, sc, bias, out);
    }
}